// round 4
// baseline (speedup 1.0000x reference)
#include <cuda_runtime.h>

#define NBATCH 16
#define NPTS   4096
#define NCTR   1024
#define NNEI   64
#define BNP    (NBATCH*NPTS)   // 65536
#define BSC    (NBATCH*NCTR)   // 16384
#define RAD2   0.04f
#define MTOT   1048576.0f
#define BNEPS  1e-5f
#define FBIG   3.402823466e38f

typedef unsigned long long u64;

// ---------------- scratch (device globals; no runtime allocation) ----------------
__device__ float g_cpos[BSC*3];
__device__ int   g_gi[BSC*NNEI];
__device__ int   g_cnt[BNP];
__device__ float g_z0[BNP*64];
__device__ float g_z1[BNP*128];
__device__ float g_A[BNP*64];
__device__ float g_D[BSC*64];
__device__ float g_zmx[BSC*128];
__device__ float g_zmn[BSC*128];
__device__ float g_p0[256*128];
__device__ float g_p1[256*256];
__device__ float g_pg0[256*128];
__device__ float g_pg1[BSC*256];
__device__ float g_pg1b[256*256];
__device__ float g_ab0[128];
__device__ float g_ab1[256];
__device__ float g_abg0[128];
__device__ float g_abg1[256];

// -------- packed fp32x2 helpers (exact: each half rounds rn, same as scalar FFMA) ---
__device__ __forceinline__ u64 pk2(float x) {
    u64 r;
    asm("mov.b64 %0, {%1, %1};" : "=l"(r) : "r"(__float_as_uint(x)));
    return r;
}
__device__ __forceinline__ void fma2(u64& d, u64 a, u64 b) {
    asm("fma.rn.f32x2 %0, %1, %2, %0;" : "+l"(d) : "l"(a), "l"(b));
}
__device__ __forceinline__ void upk(float& lo, float& hi, u64 v) {
    unsigned l, h;
    asm("mov.b64 {%0, %1}, %2;" : "=r"(l), "=r"(h) : "l"(v));
    lo = __uint_as_float(l); hi = __uint_as_float(h);
}

// ---------------- zero the multiplicity counters ----------------
__global__ void k_zero() {
    int i = blockIdx.x * 1024 + threadIdx.x;
    if (i < BNP) g_cnt[i] = 0;
}

// ---------------- 1) Farthest point sampling (1 block / batch) ----------------
// u64 key = (dist_bits << 32) | (4095 - idx): max key == max dist, first index on ties.
// One barrier per iteration: warp-reduce -> 16 shared keys (ping-pong halves) -> local max.
__global__ __launch_bounds__(512) void k_fps(const float* __restrict__ pos) {
    extern __shared__ float sm[];
    float* sx = sm;
    float* sy = sm + NPTS;
    float* sz = sm + 2*NPTS;
    u64*  skey = (u64*)(sm + 3*NPTS);   // 32 u64 (two halves of 16)

    int b = blockIdx.x, tid = threadIdx.x;
    int lane = tid & 31, w = tid >> 5;
    const float* pb = pos + b*NPTS*3;
    for (int i = tid; i < NPTS; i += 512) {
        sx[i] = pb[3*i]; sy[i] = pb[3*i+1]; sz[i] = pb[3*i+2];
    }
    __syncthreads();

    float px[8], py[8], pz[8], d[8];
#pragma unroll
    for (int j = 0; j < 8; j++) {
        int p = tid*8 + j;
        px[j] = sx[p]; py[j] = sy[p]; pz[j] = sz[p];
        d[j] = 1e10f;
    }

    int f = 0;
    float* outp = g_cpos + b*NCTR*3;
    for (int s = 0; s < NCTR; s++) {
        float cx = sx[f], cy = sy[f], cz = sz[f];
        if (tid == 0) { outp[3*s] = cx; outp[3*s+1] = cy; outp[3*s+2] = cz; }
        float bv = -1.0f; int bi = 0;
#pragma unroll
        for (int j = 0; j < 8; j++) {
            float dx = px[j]-cx, dy = py[j]-cy, dz = pz[j]-cz;
            float dd = dx*dx + dy*dy + dz*dz;
            d[j] = fminf(d[j], dd);
            if (d[j] > bv) { bv = d[j]; bi = tid*8 + j; }   // ascending j: first index wins
        }
        u64 key = ((u64)__float_as_uint(bv) << 32) | (unsigned)(4095 - bi);
#pragma unroll
        for (int o = 16; o > 0; o >>= 1) {
            u64 ok = __shfl_down_sync(0xffffffffu, key, o);
            if (ok > key) key = ok;
        }
        u64* half = skey + (s & 1) * 16;
        if (lane == 0) half[w] = key;
        __syncthreads();
        u64 m = half[0];
#pragma unroll
        for (int i = 1; i < 16; i++) { u64 v = half[i]; if (v > m) m = v; }
        f = 4095 - (int)(m & 0xFFFFu);
    }
}

// ---------------- 2) Radius-ball grouping: first 64 in-ball indices ----------------
__global__ __launch_bounds__(128) void k_group(const float* __restrict__ pos) {
    extern __shared__ float sm[];
    float* px = sm;
    float* py = sm + NPTS;
    float* pz = sm + 2*NPTS;
    float* pp = sm + 3*NPTS;
    int*   sel = (int*)(sm + 4*NPTS);     // 64
    __shared__ int s_warp[4];
    __shared__ int s_tot;

    int b = blockIdx.y;
    int tid = threadIdx.x;                 // 128 threads
    const float* pb = pos + b*NPTS*3;
    for (int i = tid; i < NPTS; i += 128) {
        float x = pb[3*i], y = pb[3*i+1], z = pb[3*i+2];
        px[i] = x; py[i] = y; pz[i] = z;
        pp[i] = (x*x + y*y) + z*z;
    }
    __syncthreads();

    for (int cs = 0; cs < 16; cs++) {
        int s = blockIdx.x*16 + cs;
        int cidx = b*NCTR + s;
        float cx = g_cpos[3*cidx], cy = g_cpos[3*cidx+1], cz = g_cpos[3*cidx+2];
        float cc = (cx*cx + cy*cy) + cz*cz;

        int base = tid*32;
        unsigned mask32 = 0; int mycnt = 0;
#pragma unroll 4
        for (int jj = 0; jj < 32; jj++) {
            int n = base + jj;
            float dot = cx*px[n] + cy*py[n] + cz*pz[n];
            float sq  = (cc - 2.0f*dot) + pp[n];
            if (!(sq > RAD2)) { mask32 |= (1u << jj); mycnt++; }
        }
        int lane = tid & 31, w = tid >> 5;
        int inc = mycnt;
#pragma unroll
        for (int o = 1; o < 32; o <<= 1) {
            int v = __shfl_up_sync(0xffffffffu, inc, o);
            if (lane >= o) inc += v;
        }
        if (lane == 31) s_warp[w] = inc;
        __syncthreads();
        int woff = 0;
        for (int i = 0; i < w; i++) woff += s_warp[i];
        int excl = woff + inc - mycnt;
        int p = excl;
        unsigned m = mask32;
        while (m && p < 64) {
            int jj = __ffs(m) - 1; m &= m - 1;
            sel[p++] = base + jj;
        }
        if (tid == 0) { int t = 0; for (int i = 0; i < 4; i++) t += s_warp[i]; s_tot = t; }
        __syncthreads();
        int tot = s_tot; if (tot > 64) tot = 64;
        if (tid >= tot && tid < 64) sel[tid] = sel[0];   // pad with first in-ball index
        __syncthreads();
        if (tid < 64) {
            int n = sel[tid];
            g_gi[cidx*64 + tid] = n;
            atomicAdd(&g_cnt[b*NPTS + n], 1);
        }
        __syncthreads();
    }
}

// ---------------- 3a) per-point semantic layer0: z0 = feat @ w0^T + b0 ----------------
__global__ __launch_bounds__(256) void k_z0(const float* __restrict__ feat,
                                            const float* __restrict__ w0,
                                            const float* __restrict__ b0) {
    __shared__ float wsh[64*64];     // [cc][c]
    __shared__ float fsh[64*68];     // [cc][row], stride 68
    int tid = threadIdx.x;
    int row0 = blockIdx.x * 64;
    for (int idx = tid; idx < 4096; idx += 256) {
        int c = idx >> 6, cc = idx & 63;
        wsh[cc*64 + c] = w0[c*64 + cc];
    }
    for (int idx = tid; idx < 4096; idx += 256) {
        int r = idx >> 6, cc = idx & 63;
        fsh[cc*68 + r] = feat[(row0 + r)*64 + cc];
    }
    __syncthreads();
    int tx = tid & 31, ty = tid >> 5;   // rows = ty*8+i, ch = tx*2+j
    u64 acc[8];
#pragma unroll
    for (int i = 0; i < 8; i++) acc[i] = 0ull;
    const u64* w64 = (const u64*)wsh;
#pragma unroll 4
    for (int cc = 0; cc < 64; cc++) {
        u64 wv = w64[cc*32 + tx];
        float4 ha = *(float4*)&fsh[cc*68 + ty*8];
        float4 hb = *(float4*)&fsh[cc*68 + ty*8 + 4];
        float hv[8] = {ha.x, ha.y, ha.z, ha.w, hb.x, hb.y, hb.z, hb.w};
#pragma unroll
        for (int i = 0; i < 8; i++) fma2(acc[i], pk2(hv[i]), wv);
    }
#pragma unroll
    for (int i = 0; i < 8; i++) {
        int r = row0 + ty*8 + i, c = tx*2;
        float lo, hi; upk(lo, hi, acc[i]);
        float2 v; v.x = lo + b0[c]; v.y = hi + b0[c+1];
        *(float2*)&g_z0[r*64 + c] = v;
    }
}

// ---------------- 3b) count-weighted stats of z0 ----------------
__global__ __launch_bounds__(256) void k_stat0() {
    __shared__ float red[512];
    int tid = threadIdx.x;
    int c = tid & 63, rg = tid >> 6;     // rg in 0..3
    int r0 = blockIdx.x * 256;
    float s1 = 0.f, s2 = 0.f;
    for (int r = r0 + rg; r < r0 + 256; r += 4) {
        float w = (float)g_cnt[r];
        float z = g_z0[r*64 + c];
        s1 += w*z; s2 += w*z*z;
    }
    red[tid] = s1; red[256 + tid] = s2;
    __syncthreads();
    if (tid < 64) {
        float a = red[tid] + red[tid+64] + red[tid+128] + red[tid+192];
        float b = red[256+tid] + red[256+tid+64] + red[256+tid+128] + red[256+tid+192];
        g_p0[blockIdx.x*128 + tid] = a;
        g_p0[blockIdx.x*128 + 64 + tid] = b;
    }
}

// ---------------- BN finalize on device-global partials (sel picks buffers) ----------
__global__ void k_fin(int sel, int nb,
                      const float* __restrict__ gm, const float* __restrict__ bt) {
    int c = threadIdx.x;
    const float* part; float* ab; int C;
    if (sel == 0)      { part = g_p0;   ab = g_ab0;  C = 64;  }
    else if (sel == 1) { part = g_p1;   ab = g_ab1;  C = 128; }
    else if (sel == 2) { part = g_pg0;  ab = g_abg0; C = 64;  }
    else               { part = g_pg1b; ab = g_abg1; C = 128; }
    float s1 = 0.f, s2 = 0.f;
    for (int r = 0; r < nb; r++) { s1 += part[r*2*C + c]; s2 += part[r*2*C + C + c]; }
    float m = s1 / MTOT;
    float v = s2 / MTOT - m*m;
    float a = gm[c] * rsqrtf(v + BNEPS);
    ab[c] = a; ab[C + c] = bt[c] - m*a;
}

// ---------------- partial reduce for geo layer1 stats (pg1 -> pg1b) ----------------
__global__ void k_red() {
    int c = threadIdx.x;               // 256
    float s = 0.f;
    int r0 = blockIdx.x * 64;
    for (int r = 0; r < 64; r++) s += g_pg1[(r0 + r)*256 + c];
    g_pg1b[blockIdx.x*256 + c] = s;
}

// ---------------- 3c) h0 = relu(a0*z0+e0); z1 = h0 @ w1^T + b1 ----------------
__global__ __launch_bounds__(256) void k_z1(const float* __restrict__ w1,
                                            const float* __restrict__ b1) {
    extern __shared__ float sm[];
    float* wsh = sm;              // [cc][c] 64x128
    float* hsh = sm + 8192;       // [cc][row], stride 68
    __shared__ float a0[64], e0[64];
    int tid = threadIdx.x;
    if (tid < 64) { a0[tid] = g_ab0[tid]; e0[tid] = g_ab0[64 + tid]; }
    int row0 = blockIdx.x * 64;
    for (int idx = tid; idx < 8192; idx += 256) {
        int c = idx >> 6, cc = idx & 63;
        wsh[cc*128 + c] = w1[idx];
    }
    __syncthreads();
    for (int idx = tid; idx < 4096; idx += 256) {
        int r = idx >> 6, cc = idx & 63;
        float z = g_z0[(row0 + r)*64 + cc];
        hsh[cc*68 + r] = fmaxf(0.f, a0[cc]*z + e0[cc]);
    }
    __syncthreads();
    int tx = tid & 31, ty = tid >> 5;   // rows = ty*8+i, ch = tx*4 + {0..3}
    u64 acc[8][2];
#pragma unroll
    for (int i = 0; i < 8; i++) { acc[i][0] = 0ull; acc[i][1] = 0ull; }
    const u64* w64 = (const u64*)wsh;
#pragma unroll 4
    for (int cc = 0; cc < 64; cc++) {
        ulonglong2 wv = *(const ulonglong2*)&w64[cc*64 + tx*2];
        float4 ha = *(float4*)&hsh[cc*68 + ty*8];
        float4 hb = *(float4*)&hsh[cc*68 + ty*8 + 4];
        float hv[8] = {ha.x, ha.y, ha.z, ha.w, hb.x, hb.y, hb.z, hb.w};
#pragma unroll
        for (int i = 0; i < 8; i++) {
            u64 h2 = pk2(hv[i]);
            fma2(acc[i][0], h2, wv.x);
            fma2(acc[i][1], h2, wv.y);
        }
    }
#pragma unroll
    for (int i = 0; i < 8; i++) {
        int r = row0 + ty*8 + i, c = tx*4;
        float l0, h0v, l1, h1v;
        upk(l0, h0v, acc[i][0]); upk(l1, h1v, acc[i][1]);
        float4 v;
        v.x = l0 + b1[c];   v.y = h0v + b1[c+1];
        v.z = l1 + b1[c+2]; v.w = h1v + b1[c+3];
        *(float4*)&g_z1[r*128 + c] = v;
    }
}

// ---------------- 3d) count-weighted stats of z1 ----------------
__global__ __launch_bounds__(256) void k_stat1() {
    __shared__ float red[512];
    int tid = threadIdx.x;
    int c = tid & 127, rg = tid >> 7;   // rg in 0..1
    int r0 = blockIdx.x * 256;
    float s1 = 0.f, s2 = 0.f;
    for (int r = r0 + rg; r < r0 + 256; r += 2) {
        float w = (float)g_cnt[r];
        float z = g_z1[r*128 + c];
        s1 += w*z; s2 += w*z*z;
    }
    red[tid] = s1; red[256 + tid] = s2;
    __syncthreads();
    if (tid < 128) {
        g_p1[blockIdx.x*256 + tid]       = red[tid] + red[tid + 128];
        g_p1[blockIdx.x*256 + 128 + tid] = red[256 + tid] + red[256 + tid + 128];
    }
}

// ---------------- 4a) geo affine precompute: A[point], D[center] ----------------
__global__ __launch_bounds__(256) void k_A(const float* __restrict__ pos,
                                           const float* __restrict__ wg0,
                                           const float* __restrict__ bg0) {
    __shared__ float u[192];
    int tid = threadIdx.x;
    if (tid < 192) { int c = tid/3, i = tid - 3*c; u[tid] = wg0[c*6 + i] + wg0[c*6 + 3 + i]; }
    __syncthreads();
    int r = blockIdx.x*4 + (tid >> 6), c = tid & 63;
    float x = pos[r*3], y = pos[r*3+1], z = pos[r*3+2];
    g_A[r*64 + c] = u[c*3]*x + u[c*3+1]*y + u[c*3+2]*z + bg0[c];
}

__global__ __launch_bounds__(256) void k_D(const float* __restrict__ wg0) {
    __shared__ float v[192];
    int tid = threadIdx.x;
    if (tid < 192) { int c = tid/3, i = tid - 3*c; v[tid] = wg0[c*6 + 3 + i]; }
    __syncthreads();
    int s = blockIdx.x*4 + (tid >> 6), c = tid & 63;
    float x = g_cpos[s*3], y = g_cpos[s*3+1], z = g_cpos[s*3+2];
    g_D[s*64 + c] = v[c*3]*x + v[c*3+1]*y + v[c*3+2]*z;
}

// ---------------- 4b) geo layer0 pair stats from per-center A sums ----------------
__global__ __launch_bounds__(64) void k_g0stats() {
    int c = threadIdx.x;                 // 64 threads
    int b = blockIdx.x >> 4;
    int s0 = (blockIdx.x & 15) * 64;
    float S1 = 0.f, S2 = 0.f;
    for (int cs = 0; cs < 64; cs++) {
        int cidx = b*NCTR + s0 + cs;
        const int* g = g_gi + cidx*64;
        float sA = 0.f, sA2 = 0.f;
        for (int k = 0; k < 64; k++) {
            int n = g[k];
            float a = g_A[(b*NPTS + n)*64 + c];
            sA += a; sA2 += a*a;
        }
        float d = g_D[cidx*64 + c];
        S1 += sA - 64.f*d;
        S2 += sA2 - 2.f*d*sA + 64.f*d*d;
    }
    g_pg0[blockIdx.x*128 + c] = S1;
    g_pg0[blockIdx.x*128 + 64 + c] = S2;
}

// ---------------- 5) big geo kernel (f32x2): h=relu(ag0*(A-D)+eg0); z = h @ wg1^T ----
// 128 threads, 8x8 per-thread tile. Per (center,channel) zmax/zmin + stat partials.
__global__ __launch_bounds__(128, 4) void k_geo(const float* __restrict__ wg1,
                                                const float* __restrict__ bg1) {
    extern __shared__ float sm[];
    float* wsh = sm;                      // 64x128  [cc][c]   = 32768 B
    float* hsh = sm + 8192;               // 64x68   [cc][k]   = 17408 B
    __shared__ float dsh[64], a0[64], e0[64];
    int tid = threadIdx.x;
    int cidx = blockIdx.x;
    int b = cidx >> 10;
    for (int idx = tid; idx < 8192; idx += 128) {
        int c = idx >> 6, cc = idx & 63;
        wsh[cc*128 + c] = wg1[idx];
    }
    if (tid < 64) {
        dsh[tid] = g_D[cidx*64 + tid];
        a0[tid] = g_abg0[tid];
        e0[tid] = g_abg0[64 + tid];
    }
    __syncthreads();
    for (int idx = tid; idx < 4096; idx += 128) {
        int k = idx >> 6, c = idx & 63;
        int n = g_gi[cidx*64 + k];
        float z = g_A[(b*NPTS + n)*64 + c] - dsh[c];
        hsh[c*68 + k] = fmaxf(0.f, a0[c]*z + e0[c]);
    }
    __syncthreads();

    int rg = tid & 7;      // rows k = rg*8 + i
    int cg = tid >> 3;     // ch   c = cg*8 + p*2 + {0,1}
    u64 acc[8][4];
#pragma unroll
    for (int i = 0; i < 8; i++)
#pragma unroll
        for (int p = 0; p < 4; p++) acc[i][p] = 0ull;
    const u64* w64 = (const u64*)wsh;
#pragma unroll 2
    for (int cc = 0; cc < 64; cc++) {
        ulonglong2 wa = *(const ulonglong2*)&w64[cc*64 + cg*4];
        ulonglong2 wb = *(const ulonglong2*)&w64[cc*64 + cg*4 + 2];
        float4 ha = *(float4*)&hsh[cc*68 + rg*8];
        float4 hb = *(float4*)&hsh[cc*68 + rg*8 + 4];
        float hv[8] = {ha.x, ha.y, ha.z, ha.w, hb.x, hb.y, hb.z, hb.w};
#pragma unroll
        for (int i = 0; i < 8; i++) {
            u64 h2 = pk2(hv[i]);
            fma2(acc[i][0], h2, wa.x);
            fma2(acc[i][1], h2, wa.y);
            fma2(acc[i][2], h2, wb.x);
            fma2(acc[i][3], h2, wb.y);
        }
    }

    // epilogue: per channel j (8 per thread): max/min/sum/sumsq over this thread's
    // 8 rows, then reduce over the 8 row-groups (lanes differing in rg bits, same warp).
    float zb[8][8];
#pragma unroll
    for (int i = 0; i < 8; i++)
#pragma unroll
        for (int p = 0; p < 4; p++)
            upk(zb[i][p*2], zb[i][p*2+1], acc[i][p]);

#pragma unroll
    for (int j = 0; j < 8; j++) {
        int c = cg*8 + j;
        float bb = bg1[c];
        float mx = -FBIG, mn = FBIG, s1 = 0.f, s2 = 0.f;
#pragma unroll
        for (int i = 0; i < 8; i++) {
            float z = zb[i][j] + bb;
            mx = fmaxf(mx, z); mn = fminf(mn, z);
            s1 += z; s2 += z*z;
        }
#pragma unroll
        for (int o = 1; o < 8; o <<= 1) {
            mx = fmaxf(mx, __shfl_xor_sync(0xffffffffu, mx, o));
            mn = fminf(mn, __shfl_xor_sync(0xffffffffu, mn, o));
            s1 += __shfl_xor_sync(0xffffffffu, s1, o);
            s2 += __shfl_xor_sync(0xffffffffu, s2, o);
        }
        if (rg == 0) {
            g_zmx[cidx*128 + c] = mx;
            g_zmn[cidx*128 + c] = mn;
            g_pg1[cidx*256 + c] = s1;
            g_pg1[cidx*256 + 128 + c] = s2;
        }
    }
}

// ---------------- 7a) semantic output: gather-max of pre-BN z1, monotone BN+relu ----
__global__ __launch_bounds__(128) void k_outsem(float* __restrict__ out) {
    int c = threadIdx.x;
    int cidx = blockIdx.x;
    int b = cidx >> 10;
    float a = g_ab1[c], e = g_ab1[128 + c];
    const int* g = g_gi + cidx*64;
    bool posa = (a >= 0.f);
    float m = posa ? -FBIG : FBIG;
#pragma unroll 4
    for (int k = 0; k < 64; k++) {
        int n = g[k];
        float z = g_z1[(b*NPTS + n)*128 + c];
        m = posa ? fmaxf(m, z) : fminf(m, z);
    }
    out[cidx*128 + c] = fmaxf(0.f, a*m + e);
}

// ---------------- 7b) geo output from zmax/zmin ----------------
__global__ __launch_bounds__(128) void k_outgeo(float* __restrict__ out) {
    int c = threadIdx.x;
    int cidx = blockIdx.x;
    float a = g_abg1[c], e = g_abg1[128 + c];
    float m = (a >= 0.f) ? g_zmx[cidx*128 + c] : g_zmn[cidx*128 + c];
    out[(BSC + cidx)*128 + c] = fmaxf(0.f, a*m + e);
}

// =============================== host ===============================
extern "C" void kernel_launch(void* const* d_in, const int* in_sizes, int n_in,
                              void* d_out, int out_size) {
    const float* pos  = (const float*)d_in[0];
    const float* feat = (const float*)d_in[1];
    const float* w0   = (const float*)d_in[2];
    const float* b0   = (const float*)d_in[3];
    const float* gm0  = (const float*)d_in[4];
    const float* bt0  = (const float*)d_in[5];
    const float* w1   = (const float*)d_in[6];
    const float* b1   = (const float*)d_in[7];
    const float* gm1  = (const float*)d_in[8];
    const float* bt1  = (const float*)d_in[9];
    const float* wg0  = (const float*)d_in[10];
    const float* bg0  = (const float*)d_in[11];
    const float* gmg0 = (const float*)d_in[12];
    const float* btg0 = (const float*)d_in[13];
    const float* wg1  = (const float*)d_in[14];
    const float* bg1  = (const float*)d_in[15];
    const float* gmg1 = (const float*)d_in[16];
    const float* btg1 = (const float*)d_in[17];
    float* out = (float*)d_out;

    cudaFuncSetAttribute(k_fps,   cudaFuncAttributeMaxDynamicSharedMemorySize, 49408);
    cudaFuncSetAttribute(k_group, cudaFuncAttributeMaxDynamicSharedMemorySize, 65792);
    cudaFuncSetAttribute(k_z1,    cudaFuncAttributeMaxDynamicSharedMemorySize, 50176);
    cudaFuncSetAttribute(k_geo,   cudaFuncAttributeMaxDynamicSharedMemorySize, 50176);

    k_zero<<<64, 1024>>>();
    k_fps<<<NBATCH, 512, 49408>>>(pos);
    k_group<<<dim3(64, NBATCH), 128, 65792>>>(pos);

    // semantic branch
    k_z0<<<BNP/64, 256>>>(feat, w0, b0);
    k_stat0<<<256, 256>>>();
    k_fin<<<1, 64>>>(0, 256, gm0, bt0);
    k_z1<<<BNP/64, 256, 50176>>>(w1, b1);
    k_stat1<<<256, 256>>>();
    k_fin<<<1, 128>>>(1, 256, gm1, bt1);

    // geo branch
    k_A<<<BNP/4, 256>>>(pos, wg0, bg0);
    k_D<<<BSC/4, 256>>>(wg0);
    k_g0stats<<<256, 64>>>();
    k_fin<<<1, 64>>>(2, 256, gmg0, btg0);
    k_geo<<<BSC, 128, 50176>>>(wg1, bg1);
    k_red<<<256, 256>>>();
    k_fin<<<1, 128>>>(3, 256, gmg1, btg1);

    // outputs
    k_outsem<<<BSC, 128>>>(out);
    k_outgeo<<<BSC, 128>>>(out);
    (void)in_sizes; (void)n_in; (void)out_size;
}

// round 5
// speedup vs baseline: 1.2148x; 1.2148x over previous
#include <cuda_runtime.h>

#define NBATCH 16
#define NPTS   4096
#define NCTR   1024
#define NNEI   64
#define BNP    (NBATCH*NPTS)   // 65536
#define BSC    (NBATCH*NCTR)   // 16384
#define RAD2   0.04f
#define MTOT   1048576.0f
#define BNEPS  1e-5f
#define FBIG   3.402823466e38f

typedef unsigned long long u64;

// ---------------- scratch (device globals; no runtime allocation) ----------------
__device__ float g_cpos[BSC*3];
__device__ int   g_gi[BSC*NNEI];
__device__ int   g_cnt[BNP];
__device__ float g_z0[BNP*64];
__device__ float g_z1[BNP*128];
__device__ float g_A[BNP*64];
__device__ float g_D[BSC*64];
__device__ float g_zmx[BSC*128];
__device__ float g_zmn[BSC*128];
__device__ float g_p0[256*128];
__device__ float g_p1[256*256];
__device__ float g_pg0[1024*128];
__device__ float g_pg0b[16*128];
__device__ float g_pg1[BSC*256];
__device__ float g_pg1b[256*256];
__device__ float g_ab0[128];
__device__ float g_ab1[256];
__device__ float g_abg0[128];
__device__ float g_abg1[256];

// -------- packed fp32x2 helpers (exact: each half rounds rn, same as scalar FFMA) ---
__device__ __forceinline__ u64 pk2(float x) {
    u64 r;
    asm("mov.b64 %0, {%1, %1};" : "=l"(r) : "r"(__float_as_uint(x)));
    return r;
}
__device__ __forceinline__ void fma2(u64& d, u64 a, u64 b) {
    asm("fma.rn.f32x2 %0, %1, %2, %0;" : "+l"(d) : "l"(a), "l"(b));
}
__device__ __forceinline__ void upk(float& lo, float& hi, u64 v) {
    unsigned l, h;
    asm("mov.b64 {%0, %1}, %2;" : "=r"(l), "=r"(h) : "l"(v));
    lo = __uint_as_float(l); hi = __uint_as_float(h);
}

// ---------------- zero the multiplicity counters ----------------
__global__ void k_zero() {
    int i = blockIdx.x * 1024 + threadIdx.x;
    if (i < BNP) g_cnt[i] = 0;
}

// ---------------- 1) Farthest point sampling (1 block / batch) ----------------
// u64 key = (dist_bits << 32) | (4095 - idx): max key == max dist, first index on ties.
__global__ __launch_bounds__(512) void k_fps(const float* __restrict__ pos) {
    extern __shared__ float sm[];
    float* sx = sm;
    float* sy = sm + NPTS;
    float* sz = sm + 2*NPTS;
    u64*  skey = (u64*)(sm + 3*NPTS);   // 32 u64 (two halves of 16)

    int b = blockIdx.x, tid = threadIdx.x;
    int lane = tid & 31, w = tid >> 5;
    const float* pb = pos + b*NPTS*3;
    for (int i = tid; i < NPTS; i += 512) {
        sx[i] = pb[3*i]; sy[i] = pb[3*i+1]; sz[i] = pb[3*i+2];
    }
    __syncthreads();

    float px[8], py[8], pz[8], d[8];
#pragma unroll
    for (int j = 0; j < 8; j++) {
        int p = tid*8 + j;
        px[j] = sx[p]; py[j] = sy[p]; pz[j] = sz[p];
        d[j] = 1e10f;
    }

    int f = 0;
    float* outp = g_cpos + b*NCTR*3;
    for (int s = 0; s < NCTR; s++) {
        float cx = sx[f], cy = sy[f], cz = sz[f];
        if (tid == 0) { outp[3*s] = cx; outp[3*s+1] = cy; outp[3*s+2] = cz; }
        float bv = -1.0f; int bi = 0;
#pragma unroll
        for (int j = 0; j < 8; j++) {
            float dx = px[j]-cx, dy = py[j]-cy, dz = pz[j]-cz;
            float dd = dx*dx + dy*dy + dz*dz;
            d[j] = fminf(d[j], dd);
            if (d[j] > bv) { bv = d[j]; bi = tid*8 + j; }   // ascending j: first index wins
        }
        u64 key = ((u64)__float_as_uint(bv) << 32) | (unsigned)(4095 - bi);
#pragma unroll
        for (int o = 16; o > 0; o >>= 1) {
            u64 ok = __shfl_down_sync(0xffffffffu, key, o);
            if (ok > key) key = ok;
        }
        u64* half = skey + (s & 1) * 16;
        if (lane == 0) half[w] = key;
        __syncthreads();
        u64 m = half[0];
#pragma unroll
        for (int i = 1; i < 16; i++) { u64 v = half[i]; if (v > m) m = v; }
        f = 4095 - (int)(m & 0xFFFFu);
    }
}

// ---------------- 2) Radius-ball grouping: first 64 in-ball indices ----------------
// Padded float4 layout: point n at p4[n + (n>>5)] -> thread t reads p4[t*33+jj],
// conflict-free LDS.128 (was a 32-way bank conflict on every scalar load).
__global__ __launch_bounds__(128) void k_group(const float* __restrict__ pos) {
    extern __shared__ float4 smq[];        // 4224 float4 (= 128*33)
    int* sel = (int*)(smq + 4224);         // 64 ints
    __shared__ int s_warp[4];
    __shared__ int s_tot;

    int b = blockIdx.y;
    int tid = threadIdx.x;                 // 128 threads
    const float* pb = pos + b*NPTS*3;
    for (int i = tid; i < NPTS; i += 128) {
        float x = pb[3*i], y = pb[3*i+1], z = pb[3*i+2];
        smq[i + (i >> 5)] = make_float4(x, y, z, (x*x + y*y) + z*z);
    }
    __syncthreads();

    const float4* myp = smq + tid*33;
    for (int cs = 0; cs < 16; cs++) {
        int s = blockIdx.x*16 + cs;
        int cidx = b*NCTR + s;
        float cx = g_cpos[3*cidx], cy = g_cpos[3*cidx+1], cz = g_cpos[3*cidx+2];
        float cc = (cx*cx + cy*cy) + cz*cz;

        int base = tid*32;
        unsigned mask32 = 0; int mycnt = 0;
#pragma unroll 4
        for (int jj = 0; jj < 32; jj++) {
            float4 q = myp[jj];
            float dot = cx*q.x + cy*q.y + cz*q.z;
            float sq  = (cc - 2.0f*dot) + q.w;
            if (!(sq > RAD2)) { mask32 |= (1u << jj); mycnt++; }
        }
        // exclusive scan over 128 threads
        int lane = tid & 31, w = tid >> 5;
        int inc = mycnt;
#pragma unroll
        for (int o = 1; o < 32; o <<= 1) {
            int v = __shfl_up_sync(0xffffffffu, inc, o);
            if (lane >= o) inc += v;
        }
        if (lane == 31) s_warp[w] = inc;
        __syncthreads();
        int woff = 0;
        for (int i = 0; i < w; i++) woff += s_warp[i];
        int excl = woff + inc - mycnt;
        int p = excl;
        unsigned m = mask32;
        while (m && p < 64) {
            int jj = __ffs(m) - 1; m &= m - 1;
            sel[p++] = base + jj;
        }
        if (tid == 0) { int t = 0; for (int i = 0; i < 4; i++) t += s_warp[i]; s_tot = t; }
        __syncthreads();
        int tot = s_tot; if (tot > 64) tot = 64;
        if (tid >= tot && tid < 64) sel[tid] = sel[0];   // pad with first in-ball index
        __syncthreads();
        if (tid < 64) {
            int n = sel[tid];
            g_gi[cidx*64 + tid] = n;
            atomicAdd(&g_cnt[b*NPTS + n], 1);
        }
        __syncthreads();
    }
}

// ---------------- 3a) per-point semantic layer0: z0 = feat @ w0^T + b0 ----------------
__global__ __launch_bounds__(256) void k_z0(const float* __restrict__ feat,
                                            const float* __restrict__ w0,
                                            const float* __restrict__ b0) {
    __shared__ float wsh[64*64];     // [cc][c]
    __shared__ float fsh[64*68];     // [cc][row], stride 68
    int tid = threadIdx.x;
    int row0 = blockIdx.x * 64;
    for (int idx = tid; idx < 4096; idx += 256) {
        int c = idx >> 6, cc = idx & 63;
        wsh[cc*64 + c] = w0[c*64 + cc];
    }
    for (int idx = tid; idx < 4096; idx += 256) {
        int r = idx >> 6, cc = idx & 63;
        fsh[cc*68 + r] = feat[(row0 + r)*64 + cc];
    }
    __syncthreads();
    int tx = tid & 31, ty = tid >> 5;   // rows = ty*8+i, ch = tx*2+j
    u64 acc[8];
#pragma unroll
    for (int i = 0; i < 8; i++) acc[i] = 0ull;
    const u64* w64 = (const u64*)wsh;
#pragma unroll 4
    for (int cc = 0; cc < 64; cc++) {
        u64 wv = w64[cc*32 + tx];
        float4 ha = *(float4*)&fsh[cc*68 + ty*8];
        float4 hb = *(float4*)&fsh[cc*68 + ty*8 + 4];
        float hv[8] = {ha.x, ha.y, ha.z, ha.w, hb.x, hb.y, hb.z, hb.w};
#pragma unroll
        for (int i = 0; i < 8; i++) fma2(acc[i], pk2(hv[i]), wv);
    }
#pragma unroll
    for (int i = 0; i < 8; i++) {
        int r = row0 + ty*8 + i, c = tx*2;
        float lo, hi; upk(lo, hi, acc[i]);
        float2 v; v.x = lo + b0[c]; v.y = hi + b0[c+1];
        *(float2*)&g_z0[r*64 + c] = v;
    }
}

// ---------------- 3b) count-weighted stats of z0 ----------------
__global__ __launch_bounds__(256) void k_stat0() {
    __shared__ float red[512];
    int tid = threadIdx.x;
    int c = tid & 63, rg = tid >> 6;     // rg in 0..3
    int r0 = blockIdx.x * 256;
    float s1 = 0.f, s2 = 0.f;
    for (int r = r0 + rg; r < r0 + 256; r += 4) {
        float w = (float)g_cnt[r];
        float z = g_z0[r*64 + c];
        s1 += w*z; s2 += w*z*z;
    }
    red[tid] = s1; red[256 + tid] = s2;
    __syncthreads();
    if (tid < 64) {
        float a = red[tid] + red[tid+64] + red[tid+128] + red[tid+192];
        float b = red[256+tid] + red[256+tid+64] + red[256+tid+128] + red[256+tid+192];
        g_p0[blockIdx.x*128 + tid] = a;
        g_p0[blockIdx.x*128 + 64 + tid] = b;
    }
}

// ---------------- BN finalize on device-global partials (sel picks buffers) ----------
__global__ void k_fin(int sel, int nb,
                      const float* __restrict__ gm, const float* __restrict__ bt) {
    int c = threadIdx.x;
    const float* part; float* ab; int C;
    if (sel == 0)      { part = g_p0;   ab = g_ab0;  C = 64;  }
    else if (sel == 1) { part = g_p1;   ab = g_ab1;  C = 128; }
    else if (sel == 2) { part = g_pg0b; ab = g_abg0; C = 64;  }
    else               { part = g_pg1b; ab = g_abg1; C = 128; }
    float s1 = 0.f, s2 = 0.f;
    for (int r = 0; r < nb; r++) { s1 += part[r*2*C + c]; s2 += part[r*2*C + C + c]; }
    float m = s1 / MTOT;
    float v = s2 / MTOT - m*m;
    float a = gm[c] * rsqrtf(v + BNEPS);
    ab[c] = a; ab[C + c] = bt[c] - m*a;
}

// ---------------- partial reduce for geo layer1 stats (pg1 -> pg1b) ----------------
__global__ void k_red() {
    int c = threadIdx.x;               // 256
    float s = 0.f;
    int r0 = blockIdx.x * 64;
    for (int r = 0; r < 64; r++) s += g_pg1[(r0 + r)*256 + c];
    g_pg1b[blockIdx.x*256 + c] = s;
}

// ---------------- partial reduce for geo layer0 stats (pg0 -> pg0b) ----------------
__global__ void k_redg0() {
    int c = threadIdx.x;               // 128
    float s = 0.f;
    int r0 = blockIdx.x * 64;
    for (int r = 0; r < 64; r++) s += g_pg0[(r0 + r)*128 + c];
    g_pg0b[blockIdx.x*128 + c] = s;
}

// ---------------- 3c) h0 = relu(a0*z0+e0); z1 = h0 @ w1^T + b1 ----------------
__global__ __launch_bounds__(256) void k_z1(const float* __restrict__ w1,
                                            const float* __restrict__ b1) {
    extern __shared__ float sm[];
    float* wsh = sm;              // [cc][c] 64x128
    float* hsh = sm + 8192;       // [cc][row], stride 68
    __shared__ float a0[64], e0[64];
    int tid = threadIdx.x;
    if (tid < 64) { a0[tid] = g_ab0[tid]; e0[tid] = g_ab0[64 + tid]; }
    int row0 = blockIdx.x * 64;
    for (int idx = tid; idx < 8192; idx += 256) {
        int c = idx >> 6, cc = idx & 63;
        wsh[cc*128 + c] = w1[idx];
    }
    __syncthreads();
    for (int idx = tid; idx < 4096; idx += 256) {
        int r = idx >> 6, cc = idx & 63;
        float z = g_z0[(row0 + r)*64 + cc];
        hsh[cc*68 + r] = fmaxf(0.f, a0[cc]*z + e0[cc]);
    }
    __syncthreads();
    int tx = tid & 31, ty = tid >> 5;   // rows = ty*8+i, ch = tx*4 + {0..3}
    u64 acc[8][2];
#pragma unroll
    for (int i = 0; i < 8; i++) { acc[i][0] = 0ull; acc[i][1] = 0ull; }
    const u64* w64 = (const u64*)wsh;
#pragma unroll 4
    for (int cc = 0; cc < 64; cc++) {
        ulonglong2 wv = *(const ulonglong2*)&w64[cc*64 + tx*2];
        float4 ha = *(float4*)&hsh[cc*68 + ty*8];
        float4 hb = *(float4*)&hsh[cc*68 + ty*8 + 4];
        float hv[8] = {ha.x, ha.y, ha.z, ha.w, hb.x, hb.y, hb.z, hb.w};
#pragma unroll
        for (int i = 0; i < 8; i++) {
            u64 h2 = pk2(hv[i]);
            fma2(acc[i][0], h2, wv.x);
            fma2(acc[i][1], h2, wv.y);
        }
    }
#pragma unroll
    for (int i = 0; i < 8; i++) {
        int r = row0 + ty*8 + i, c = tx*4;
        float l0, h0v, l1, h1v;
        upk(l0, h0v, acc[i][0]); upk(l1, h1v, acc[i][1]);
        float4 v;
        v.x = l0 + b1[c];   v.y = h0v + b1[c+1];
        v.z = l1 + b1[c+2]; v.w = h1v + b1[c+3];
        *(float4*)&g_z1[r*128 + c] = v;
    }
}

// ---------------- 3d) count-weighted stats of z1 ----------------
__global__ __launch_bounds__(256) void k_stat1() {
    __shared__ float red[512];
    int tid = threadIdx.x;
    int c = tid & 127, rg = tid >> 7;   // rg in 0..1
    int r0 = blockIdx.x * 256;
    float s1 = 0.f, s2 = 0.f;
    for (int r = r0 + rg; r < r0 + 256; r += 2) {
        float w = (float)g_cnt[r];
        float z = g_z1[r*128 + c];
        s1 += w*z; s2 += w*z*z;
    }
    red[tid] = s1; red[256 + tid] = s2;
    __syncthreads();
    if (tid < 128) {
        g_p1[blockIdx.x*256 + tid]       = red[tid] + red[tid + 128];
        g_p1[blockIdx.x*256 + 128 + tid] = red[256 + tid] + red[256 + tid + 128];
    }
}

// ---------------- 4a) geo affine precompute: A[point], D[center] ----------------
__global__ __launch_bounds__(256) void k_A(const float* __restrict__ pos,
                                           const float* __restrict__ wg0,
                                           const float* __restrict__ bg0) {
    __shared__ float u[192];
    int tid = threadIdx.x;
    if (tid < 192) { int c = tid/3, i = tid - 3*c; u[tid] = wg0[c*6 + i] + wg0[c*6 + 3 + i]; }
    __syncthreads();
    int r = blockIdx.x*4 + (tid >> 6), c = tid & 63;
    float x = pos[r*3], y = pos[r*3+1], z = pos[r*3+2];
    g_A[r*64 + c] = u[c*3]*x + u[c*3+1]*y + u[c*3+2]*z + bg0[c];
}

__global__ __launch_bounds__(256) void k_D(const float* __restrict__ wg0) {
    __shared__ float v[192];
    int tid = threadIdx.x;
    if (tid < 192) { int c = tid/3, i = tid - 3*c; v[tid] = wg0[c*6 + 3 + i]; }
    __syncthreads();
    int s = blockIdx.x*4 + (tid >> 6), c = tid & 63;
    float x = g_cpos[s*3], y = g_cpos[s*3+1], z = g_cpos[s*3+2];
    g_D[s*64 + c] = v[c*3]*x + v[c*3+1]*y + v[c*3+2]*z;
}

// ---------------- 4b) geo layer0 pair stats from per-center A sums ----------------
__global__ __launch_bounds__(64) void k_g0stats() {
    int c = threadIdx.x;                 // 64 threads
    int b = blockIdx.x >> 6;
    int s0 = (blockIdx.x & 63) * 16;
    float S1 = 0.f, S2 = 0.f;
    for (int cs = 0; cs < 16; cs++) {
        int cidx = b*NCTR + s0 + cs;
        const int* g = g_gi + cidx*64;
        float sA = 0.f, sA2 = 0.f;
#pragma unroll 8
        for (int k = 0; k < 64; k++) {
            int n = g[k];
            float a = g_A[(b*NPTS + n)*64 + c];
            sA += a; sA2 += a*a;
        }
        float d = g_D[cidx*64 + c];
        S1 += sA - 64.f*d;
        S2 += sA2 - 2.f*d*sA + 64.f*d*d;
    }
    g_pg0[blockIdx.x*128 + c] = S1;
    g_pg0[blockIdx.x*128 + 64 + c] = S2;
}

// ---------------- 5) big geo kernel (f32x2): h=relu(ag0*(A-D)+eg0); z = h @ wg1^T ----
__global__ __launch_bounds__(128, 4) void k_geo(const float* __restrict__ wg1,
                                                const float* __restrict__ bg1) {
    extern __shared__ float sm[];
    float* wsh = sm;                      // 64x128  [cc][c]   = 32768 B
    float* hsh = sm + 8192;               // 64x68   [cc][k]   = 17408 B
    __shared__ float dsh[64], a0[64], e0[64];
    int tid = threadIdx.x;
    int cidx = blockIdx.x;
    int b = cidx >> 10;
    for (int idx = tid; idx < 8192; idx += 128) {
        int c = idx >> 6, cc = idx & 63;
        wsh[cc*128 + c] = wg1[idx];
    }
    if (tid < 64) {
        dsh[tid] = g_D[cidx*64 + tid];
        a0[tid] = g_abg0[tid];
        e0[tid] = g_abg0[64 + tid];
    }
    __syncthreads();
    for (int idx = tid; idx < 4096; idx += 128) {
        int k = idx >> 6, c = idx & 63;
        int n = g_gi[cidx*64 + k];
        float z = g_A[(b*NPTS + n)*64 + c] - dsh[c];
        hsh[c*68 + k] = fmaxf(0.f, a0[c]*z + e0[c]);
    }
    __syncthreads();

    int rg = tid & 7;      // rows k = rg*8 + i
    int cg = tid >> 3;     // ch   c = cg*8 + p*2 + {0,1}
    u64 acc[8][4];
#pragma unroll
    for (int i = 0; i < 8; i++)
#pragma unroll
        for (int p = 0; p < 4; p++) acc[i][p] = 0ull;
    const u64* w64 = (const u64*)wsh;
#pragma unroll 2
    for (int cc = 0; cc < 64; cc++) {
        ulonglong2 wa = *(const ulonglong2*)&w64[cc*64 + cg*4];
        ulonglong2 wb = *(const ulonglong2*)&w64[cc*64 + cg*4 + 2];
        float4 ha = *(float4*)&hsh[cc*68 + rg*8];
        float4 hb = *(float4*)&hsh[cc*68 + rg*8 + 4];
        float hv[8] = {ha.x, ha.y, ha.z, ha.w, hb.x, hb.y, hb.z, hb.w};
#pragma unroll
        for (int i = 0; i < 8; i++) {
            u64 h2 = pk2(hv[i]);
            fma2(acc[i][0], h2, wa.x);
            fma2(acc[i][1], h2, wa.y);
            fma2(acc[i][2], h2, wb.x);
            fma2(acc[i][3], h2, wb.y);
        }
    }

    float zb[8][8];
#pragma unroll
    for (int i = 0; i < 8; i++)
#pragma unroll
        for (int p = 0; p < 4; p++)
            upk(zb[i][p*2], zb[i][p*2+1], acc[i][p]);

#pragma unroll
    for (int j = 0; j < 8; j++) {
        int c = cg*8 + j;
        float bb = bg1[c];
        float mx = -FBIG, mn = FBIG, s1 = 0.f, s2 = 0.f;
#pragma unroll
        for (int i = 0; i < 8; i++) {
            float z = zb[i][j] + bb;
            mx = fmaxf(mx, z); mn = fminf(mn, z);
            s1 += z; s2 += z*z;
        }
#pragma unroll
        for (int o = 1; o < 8; o <<= 1) {
            mx = fmaxf(mx, __shfl_xor_sync(0xffffffffu, mx, o));
            mn = fminf(mn, __shfl_xor_sync(0xffffffffu, mn, o));
            s1 += __shfl_xor_sync(0xffffffffu, s1, o);
            s2 += __shfl_xor_sync(0xffffffffu, s2, o);
        }
        if (rg == 0) {
            g_zmx[cidx*128 + c] = mx;
            g_zmn[cidx*128 + c] = mn;
            g_pg1[cidx*256 + c] = s1;
            g_pg1[cidx*256 + 128 + c] = s2;
        }
    }
}

// ---------------- 7a) semantic output: gather-max of pre-BN z1, monotone BN+relu ----
__global__ __launch_bounds__(128) void k_outsem(float* __restrict__ out) {
    int c = threadIdx.x;
    int cidx = blockIdx.x;
    int b = cidx >> 10;
    float a = g_ab1[c], e = g_ab1[128 + c];
    const int* g = g_gi + cidx*64;
    bool posa = (a >= 0.f);
    float m = posa ? -FBIG : FBIG;
#pragma unroll 4
    for (int k = 0; k < 64; k++) {
        int n = g[k];
        float z = g_z1[(b*NPTS + n)*128 + c];
        m = posa ? fmaxf(m, z) : fminf(m, z);
    }
    out[cidx*128 + c] = fmaxf(0.f, a*m + e);
}

// ---------------- 7b) geo output from zmax/zmin ----------------
__global__ __launch_bounds__(128) void k_outgeo(float* __restrict__ out) {
    int c = threadIdx.x;
    int cidx = blockIdx.x;
    float a = g_abg1[c], e = g_abg1[128 + c];
    float m = (a >= 0.f) ? g_zmx[cidx*128 + c] : g_zmn[cidx*128 + c];
    out[(BSC + cidx)*128 + c] = fmaxf(0.f, a*m + e);
}

// =============================== host ===============================
extern "C" void kernel_launch(void* const* d_in, const int* in_sizes, int n_in,
                              void* d_out, int out_size) {
    const float* pos  = (const float*)d_in[0];
    const float* feat = (const float*)d_in[1];
    const float* w0   = (const float*)d_in[2];
    const float* b0   = (const float*)d_in[3];
    const float* gm0  = (const float*)d_in[4];
    const float* bt0  = (const float*)d_in[5];
    const float* w1   = (const float*)d_in[6];
    const float* b1   = (const float*)d_in[7];
    const float* gm1  = (const float*)d_in[8];
    const float* bt1  = (const float*)d_in[9];
    const float* wg0  = (const float*)d_in[10];
    const float* bg0  = (const float*)d_in[11];
    const float* gmg0 = (const float*)d_in[12];
    const float* btg0 = (const float*)d_in[13];
    const float* wg1  = (const float*)d_in[14];
    const float* bg1  = (const float*)d_in[15];
    const float* gmg1 = (const float*)d_in[16];
    const float* btg1 = (const float*)d_in[17];
    float* out = (float*)d_out;

    cudaFuncSetAttribute(k_fps,   cudaFuncAttributeMaxDynamicSharedMemorySize, 49408);
    cudaFuncSetAttribute(k_group, cudaFuncAttributeMaxDynamicSharedMemorySize, 67840);
    cudaFuncSetAttribute(k_z1,    cudaFuncAttributeMaxDynamicSharedMemorySize, 50176);
    cudaFuncSetAttribute(k_geo,   cudaFuncAttributeMaxDynamicSharedMemorySize, 50176);

    k_zero<<<64, 1024>>>();
    k_fps<<<NBATCH, 512, 49408>>>(pos);
    k_group<<<dim3(64, NBATCH), 128, 67840>>>(pos);

    // semantic branch
    k_z0<<<BNP/64, 256>>>(feat, w0, b0);
    k_stat0<<<256, 256>>>();
    k_fin<<<1, 64>>>(0, 256, gm0, bt0);
    k_z1<<<BNP/64, 256, 50176>>>(w1, b1);
    k_stat1<<<256, 256>>>();
    k_fin<<<1, 128>>>(1, 256, gm1, bt1);

    // geo branch
    k_A<<<BNP/4, 256>>>(pos, wg0, bg0);
    k_D<<<BSC/4, 256>>>(wg0);
    k_g0stats<<<1024, 64>>>();
    k_redg0<<<16, 128>>>();
    k_fin<<<1, 64>>>(2, 16, gmg0, btg0);
    k_geo<<<BSC, 128, 50176>>>(wg1, bg1);
    k_red<<<256, 256>>>();
    k_fin<<<1, 128>>>(3, 256, gmg1, btg1);

    // outputs
    k_outsem<<<BSC, 128>>>(out);
    k_outgeo<<<BSC, 128>>>(out);
    (void)in_sizes; (void)n_in; (void)out_size;
}

// round 6
// speedup vs baseline: 1.2644x; 1.0408x over previous
#include <cuda_runtime.h>

#define NBATCH 16
#define NPTS   4096
#define NCTR   1024
#define NNEI   64
#define BNP    (NBATCH*NPTS)   // 65536
#define BSC    (NBATCH*NCTR)   // 16384
#define RAD2   0.04f
#define MTOT   1048576.0f
#define BNEPS  1e-5f
#define FBIG   3.402823466e38f

typedef unsigned long long u64;

// ---------------- scratch (device globals; no runtime allocation) ----------------
__device__ float g_cpos[BSC*3];
__device__ int   g_gi[BSC*NNEI];
__device__ int   g_cnt[BNP];
__device__ float g_z0[BNP*64];
__device__ float g_z1[BNP*128];
__device__ float g_A[BNP*64];
__device__ float g_D[BSC*64];
__device__ float g_zmx[BSC*128];
__device__ float g_zmn[BSC*128];
__device__ float g_p0[256*128];
__device__ float g_p1[256*256];
__device__ float g_pg0[1024*128];
__device__ float g_pg0b[16*128];
__device__ float g_pg1[BSC*256];
__device__ float g_pg1b[256*256];
__device__ float g_ab0[128];
__device__ float g_ab1[256];
__device__ float g_abg0[128];
__device__ float g_abg1[256];

// -------- packed fp32x2 helpers (exact: each half rounds rn, same as scalar FFMA) ---
__device__ __forceinline__ u64 pk2(float x) {
    u64 r;
    asm("mov.b64 %0, {%1, %1};" : "=l"(r) : "r"(__float_as_uint(x)));
    return r;
}
__device__ __forceinline__ void fma2(u64& d, u64 a, u64 b) {
    asm("fma.rn.f32x2 %0, %1, %2, %0;" : "+l"(d) : "l"(a), "l"(b));
}
__device__ __forceinline__ void upk(float& lo, float& hi, u64 v) {
    unsigned l, h;
    asm("mov.b64 {%0, %1}, %2;" : "=r"(l), "=r"(h) : "l"(v));
    lo = __uint_as_float(l); hi = __uint_as_float(h);
}

// ---------------- zero the multiplicity counters ----------------
__global__ void k_zero() {
    int i = blockIdx.x * 1024 + threadIdx.x;
    if (i < BNP) g_cnt[i] = 0;
}

// ======================= fused front kernel =======================
// blocks 0..15            : FPS (1 per batch)
// blocks 16..1039         : semantic layer0 z0 (64 rows each)
// blocks 1040..9231       : geo affine A (8 rows each)
// All three parts are mutually independent; FPS is the serial tail that the
// other blocks hide.
__global__ __launch_bounds__(512) void k_front(const float* __restrict__ pos,
                                               const float* __restrict__ feat,
                                               const float* __restrict__ w0,
                                               const float* __restrict__ b0,
                                               const float* __restrict__ wg0,
                                               const float* __restrict__ bg0) {
    extern __shared__ float sm[];
    int tid = threadIdx.x;

    if (blockIdx.x < 16) {
        // ---------------- FPS ----------------
        float* sx = sm;
        float* sy = sm + NPTS;
        float* sz = sm + 2*NPTS;
        u64*  skey = (u64*)(sm + 3*NPTS);   // 32 u64 (ping-pong halves of 16)

        int b = blockIdx.x;
        int lane = tid & 31, w = tid >> 5;
        const float* pb = pos + b*NPTS*3;
        for (int i = tid; i < NPTS; i += 512) {
            sx[i] = pb[3*i]; sy[i] = pb[3*i+1]; sz[i] = pb[3*i+2];
        }
        __syncthreads();

        float px[8], py[8], pz[8], d[8];
#pragma unroll
        for (int j = 0; j < 8; j++) {
            int p = tid*8 + j;
            px[j] = sx[p]; py[j] = sy[p]; pz[j] = sz[p];
            d[j] = 1e10f;
        }

        int f = 0;
        float* outp = g_cpos + b*NCTR*3;
        for (int s = 0; s < NCTR; s++) {
            float cx = sx[f], cy = sy[f], cz = sz[f];
            if (tid == 0) { outp[3*s] = cx; outp[3*s+1] = cy; outp[3*s+2] = cz; }
            float lv = -1.0f; int bi = 0;
#pragma unroll
            for (int j = 0; j < 8; j++) {
                float dx = px[j]-cx, dy = py[j]-cy, dz = pz[j]-cz;
                float dd = dx*dx + dy*dy + dz*dz;
                d[j] = fminf(d[j], dd);
                if (d[j] > lv) { lv = d[j]; bi = tid*8 + j; }   // ascending j: first wins
            }
            // 32-bit all-reduce max, then ballot for first (lowest-index) holder
            float mx = lv;
#pragma unroll
            for (int o = 16; o > 0; o >>= 1)
                mx = fmaxf(mx, __shfl_xor_sync(0xffffffffu, mx, o));
            unsigned ball = __ballot_sync(0xffffffffu, lv == mx);
            int src = __ffs(ball) - 1;                          // lowest lane = lowest index
            int wbi = __shfl_sync(0xffffffffu, bi, src);
            u64* half = skey + (s & 1) * 16;
            if (lane == 0)
                half[w] = ((u64)__float_as_uint(mx) << 32) | (unsigned)(4095 - wbi);
            __syncthreads();
            u64 v[16];
#pragma unroll
            for (int i = 0; i < 16; i++) v[i] = half[i];
#pragma unroll
            for (int st = 8; st > 0; st >>= 1)
#pragma unroll
                for (int i = 0; i < 8; i++)
                    if (i < st && v[i + st] > v[i]) v[i] = v[i + st];
            f = 4095 - (int)(v[0] & 0xFFFFu);
        }
    } else if (blockIdx.x < 16 + 1024) {
        // ---------------- semantic layer0: z0 = feat @ w0^T + b0 (64 rows) ----------
        float* wsh = sm;            // 64x64  [cc][c]
        float* fsh = sm + 4096;     // 64x68  [cc][row]
        int row0 = (blockIdx.x - 16) * 64;
        for (int idx = tid; idx < 4096; idx += 512) {
            int c = idx >> 6, cc = idx & 63;
            wsh[cc*64 + c] = w0[c*64 + cc];
        }
        for (int idx = tid; idx < 4096; idx += 512) {
            int r = idx >> 6, cc = idx & 63;
            fsh[cc*68 + r] = feat[(row0 + r)*64 + cc];
        }
        __syncthreads();
        int tx = tid & 31, ty = tid >> 5;   // rows = ty*4+i, ch = tx*2+{0,1}
        u64 acc[4];
#pragma unroll
        for (int i = 0; i < 4; i++) acc[i] = 0ull;
        const u64* w64 = (const u64*)wsh;
#pragma unroll 4
        for (int cc = 0; cc < 64; cc++) {
            u64 wv = w64[cc*32 + tx];
            float4 ha = *(float4*)&fsh[cc*68 + ty*4];
            fma2(acc[0], pk2(ha.x), wv);
            fma2(acc[1], pk2(ha.y), wv);
            fma2(acc[2], pk2(ha.z), wv);
            fma2(acc[3], pk2(ha.w), wv);
        }
#pragma unroll
        for (int i = 0; i < 4; i++) {
            int r = row0 + ty*4 + i, c = tx*2;
            float lo, hi; upk(lo, hi, acc[i]);
            float2 vv; vv.x = lo + b0[c]; vv.y = hi + b0[c+1];
            *(float2*)&g_z0[r*64 + c] = vv;
        }
    } else {
        // ---------------- geo affine A (8 rows) ----------------
        float* u = sm;              // 192 floats
        if (tid < 192) {
            int c = tid/3, i = tid - 3*c;
            u[tid] = wg0[c*6 + i] + wg0[c*6 + 3 + i];
        }
        __syncthreads();
        int r = (blockIdx.x - 1040)*8 + (tid >> 6), c = tid & 63;
        float x = pos[r*3], y = pos[r*3+1], z = pos[r*3+2];
        g_A[r*64 + c] = u[c*3]*x + u[c*3+1]*y + u[c*3+2]*z + bg0[c];
    }
}

// ---------------- 2) Radius-ball grouping: first 64 in-ball indices ----------------
__global__ __launch_bounds__(128) void k_group(const float* __restrict__ pos) {
    extern __shared__ float4 smq[];        // 4224 float4 (= 128*33, padded)
    int* sel = (int*)(smq + 4224);         // 64 ints
    __shared__ int s_warp[4];
    __shared__ int s_tot;

    int b = blockIdx.y;
    int tid = threadIdx.x;                 // 128 threads
    const float* pb = pos + b*NPTS*3;
    for (int i = tid; i < NPTS; i += 128) {
        float x = pb[3*i], y = pb[3*i+1], z = pb[3*i+2];
        smq[i + (i >> 5)] = make_float4(x, y, z, (x*x + y*y) + z*z);
    }
    __syncthreads();

    const float4* myp = smq + tid*33;
    for (int cs = 0; cs < 16; cs++) {
        int s = blockIdx.x*16 + cs;
        int cidx = b*NCTR + s;
        float cx = g_cpos[3*cidx], cy = g_cpos[3*cidx+1], cz = g_cpos[3*cidx+2];
        float cc = (cx*cx + cy*cy) + cz*cz;

        int base = tid*32;
        unsigned mask32 = 0; int mycnt = 0;
#pragma unroll 4
        for (int jj = 0; jj < 32; jj++) {
            float4 q = myp[jj];
            float dot = cx*q.x + cy*q.y + cz*q.z;
            float sq  = (cc - 2.0f*dot) + q.w;
            if (!(sq > RAD2)) { mask32 |= (1u << jj); mycnt++; }
        }
        int lane = tid & 31, w = tid >> 5;
        int inc = mycnt;
#pragma unroll
        for (int o = 1; o < 32; o <<= 1) {
            int v = __shfl_up_sync(0xffffffffu, inc, o);
            if (lane >= o) inc += v;
        }
        if (lane == 31) s_warp[w] = inc;
        __syncthreads();
        int woff = 0;
        for (int i = 0; i < w; i++) woff += s_warp[i];
        int excl = woff + inc - mycnt;
        int p = excl;
        unsigned m = mask32;
        while (m && p < 64) {
            int jj = __ffs(m) - 1; m &= m - 1;
            sel[p++] = base + jj;
        }
        if (tid == 0) { int t = 0; for (int i = 0; i < 4; i++) t += s_warp[i]; s_tot = t; }
        __syncthreads();
        int tot = s_tot; if (tot > 64) tot = 64;
        if (tid >= tot && tid < 64) sel[tid] = sel[0];   // pad with first in-ball index
        __syncthreads();
        if (tid < 64) {
            int n = sel[tid];
            g_gi[cidx*64 + tid] = n;
            atomicAdd(&g_cnt[b*NPTS + n], 1);
        }
        __syncthreads();
    }
}

// ---------------- 3b) count-weighted stats of z0 ----------------
__global__ __launch_bounds__(256) void k_stat0() {
    __shared__ float red[512];
    int tid = threadIdx.x;
    int c = tid & 63, rg = tid >> 6;     // rg in 0..3
    int r0 = blockIdx.x * 256;
    float s1 = 0.f, s2 = 0.f;
    for (int r = r0 + rg; r < r0 + 256; r += 4) {
        float w = (float)g_cnt[r];
        float z = g_z0[r*64 + c];
        s1 += w*z; s2 += w*z*z;
    }
    red[tid] = s1; red[256 + tid] = s2;
    __syncthreads();
    if (tid < 64) {
        float a = red[tid] + red[tid+64] + red[tid+128] + red[tid+192];
        float b = red[256+tid] + red[256+tid+64] + red[256+tid+128] + red[256+tid+192];
        g_p0[blockIdx.x*128 + tid] = a;
        g_p0[blockIdx.x*128 + 64 + tid] = b;
    }
}

// ---------------- BN finalize on device-global partials (sel picks buffers) ----------
__global__ void k_fin(int sel, int nb,
                      const float* __restrict__ gm, const float* __restrict__ bt) {
    int c = threadIdx.x;
    const float* part; float* ab; int C;
    if (sel == 0)      { part = g_p0;   ab = g_ab0;  C = 64;  }
    else if (sel == 1) { part = g_p1;   ab = g_ab1;  C = 128; }
    else if (sel == 2) { part = g_pg0b; ab = g_abg0; C = 64;  }
    else               { part = g_pg1b; ab = g_abg1; C = 128; }
    float s1 = 0.f, s2 = 0.f;
    for (int r = 0; r < nb; r++) { s1 += part[r*2*C + c]; s2 += part[r*2*C + C + c]; }
    float m = s1 / MTOT;
    float v = s2 / MTOT - m*m;
    float a = gm[c] * rsqrtf(v + BNEPS);
    ab[c] = a; ab[C + c] = bt[c] - m*a;
}

// ---------------- partial reduce for geo layer1 stats (pg1 -> pg1b) ----------------
__global__ void k_red() {
    int c = threadIdx.x;               // 256
    float s = 0.f;
    int r0 = blockIdx.x * 64;
    for (int r = 0; r < 64; r++) s += g_pg1[(r0 + r)*256 + c];
    g_pg1b[blockIdx.x*256 + c] = s;
}

// ---------------- partial reduce for geo layer0 stats (pg0 -> pg0b) ----------------
__global__ void k_redg0() {
    int c = threadIdx.x;               // 128
    float s = 0.f;
    int r0 = blockIdx.x * 64;
    for (int r = 0; r < 64; r++) s += g_pg0[(r0 + r)*128 + c];
    g_pg0b[blockIdx.x*128 + c] = s;
}

// ---------------- 3c) h0 = relu(a0*z0+e0); z1 = h0 @ w1^T + b1 ----------------
__global__ __launch_bounds__(256) void k_z1(const float* __restrict__ w1,
                                            const float* __restrict__ b1) {
    extern __shared__ float sm[];
    float* wsh = sm;              // [cc][c] 64x128
    float* hsh = sm + 8192;       // [cc][row], stride 68
    __shared__ float a0[64], e0[64];
    int tid = threadIdx.x;
    if (tid < 64) { a0[tid] = g_ab0[tid]; e0[tid] = g_ab0[64 + tid]; }
    int row0 = blockIdx.x * 64;
    for (int idx = tid; idx < 8192; idx += 256) {
        int c = idx >> 6, cc = idx & 63;
        wsh[cc*128 + c] = w1[idx];
    }
    __syncthreads();
    for (int idx = tid; idx < 4096; idx += 256) {
        int r = idx >> 6, cc = idx & 63;
        float z = g_z0[(row0 + r)*64 + cc];
        hsh[cc*68 + r] = fmaxf(0.f, a0[cc]*z + e0[cc]);
    }
    __syncthreads();
    int tx = tid & 31, ty = tid >> 5;   // rows = ty*8+i, ch = tx*4 + {0..3}
    u64 acc[8][2];
#pragma unroll
    for (int i = 0; i < 8; i++) { acc[i][0] = 0ull; acc[i][1] = 0ull; }
    const u64* w64 = (const u64*)wsh;
#pragma unroll 4
    for (int cc = 0; cc < 64; cc++) {
        ulonglong2 wv = *(const ulonglong2*)&w64[cc*64 + tx*2];
        float4 ha = *(float4*)&hsh[cc*68 + ty*8];
        float4 hb = *(float4*)&hsh[cc*68 + ty*8 + 4];
        float hv[8] = {ha.x, ha.y, ha.z, ha.w, hb.x, hb.y, hb.z, hb.w};
#pragma unroll
        for (int i = 0; i < 8; i++) {
            u64 h2 = pk2(hv[i]);
            fma2(acc[i][0], h2, wv.x);
            fma2(acc[i][1], h2, wv.y);
        }
    }
#pragma unroll
    for (int i = 0; i < 8; i++) {
        int r = row0 + ty*8 + i, c = tx*4;
        float l0, h0v, l1, h1v;
        upk(l0, h0v, acc[i][0]); upk(l1, h1v, acc[i][1]);
        float4 v;
        v.x = l0 + b1[c];   v.y = h0v + b1[c+1];
        v.z = l1 + b1[c+2]; v.w = h1v + b1[c+3];
        *(float4*)&g_z1[r*128 + c] = v;
    }
}

// ---------------- 3d) count-weighted stats of z1 ----------------
__global__ __launch_bounds__(256) void k_stat1() {
    __shared__ float red[512];
    int tid = threadIdx.x;
    int c = tid & 127, rg = tid >> 7;   // rg in 0..1
    int r0 = blockIdx.x * 256;
    float s1 = 0.f, s2 = 0.f;
    for (int r = r0 + rg; r < r0 + 256; r += 2) {
        float w = (float)g_cnt[r];
        float z = g_z1[r*128 + c];
        s1 += w*z; s2 += w*z*z;
    }
    red[tid] = s1; red[256 + tid] = s2;
    __syncthreads();
    if (tid < 128) {
        g_p1[blockIdx.x*256 + tid]       = red[tid] + red[tid + 128];
        g_p1[blockIdx.x*256 + 128 + tid] = red[256 + tid] + red[256 + tid + 128];
    }
}

// ---------------- 4a) geo affine D[center] ----------------
__global__ __launch_bounds__(256) void k_D(const float* __restrict__ wg0) {
    __shared__ float v[192];
    int tid = threadIdx.x;
    if (tid < 192) { int c = tid/3, i = tid - 3*c; v[tid] = wg0[c*6 + 3 + i]; }
    __syncthreads();
    int s = blockIdx.x*4 + (tid >> 6), c = tid & 63;
    float x = g_cpos[s*3], y = g_cpos[s*3+1], z = g_cpos[s*3+2];
    g_D[s*64 + c] = v[c*3]*x + v[c*3+1]*y + v[c*3+2]*z;
}

// ---------------- 4b) geo layer0 pair stats from per-center A sums ----------------
__global__ __launch_bounds__(64) void k_g0stats() {
    int c = threadIdx.x;                 // 64 threads
    int b = blockIdx.x >> 6;
    int s0 = (blockIdx.x & 63) * 16;
    float S1 = 0.f, S2 = 0.f;
    for (int cs = 0; cs < 16; cs++) {
        int cidx = b*NCTR + s0 + cs;
        const int* g = g_gi + cidx*64;
        float sA = 0.f, sA2 = 0.f;
#pragma unroll 8
        for (int k = 0; k < 64; k++) {
            int n = g[k];
            float a = g_A[(b*NPTS + n)*64 + c];
            sA += a; sA2 += a*a;
        }
        float d = g_D[cidx*64 + c];
        S1 += sA - 64.f*d;
        S2 += sA2 - 2.f*d*sA + 64.f*d*d;
    }
    g_pg0[blockIdx.x*128 + c] = S1;
    g_pg0[blockIdx.x*128 + 64 + c] = S2;
}

// ---------------- 5) big geo kernel (f32x2): h=relu(ag0*(A-D)+eg0); z = h @ wg1^T ----
// Epilogue streams one accumulator column at a time (no zb[8][8] materialization ->
// no register spill under the 128-reg cap).
__global__ __launch_bounds__(128, 4) void k_geo(const float* __restrict__ wg1,
                                                const float* __restrict__ bg1) {
    extern __shared__ float sm[];
    float* wsh = sm;                      // 64x128  [cc][c]   = 32768 B
    float* hsh = sm + 8192;               // 64x68   [cc][k]   = 17408 B
    __shared__ float dsh[64], a0[64], e0[64];
    int tid = threadIdx.x;
    int cidx = blockIdx.x;
    int b = cidx >> 10;
    for (int idx = tid; idx < 8192; idx += 128) {
        int c = idx >> 6, cc = idx & 63;
        wsh[cc*128 + c] = wg1[idx];
    }
    if (tid < 64) {
        dsh[tid] = g_D[cidx*64 + tid];
        a0[tid] = g_abg0[tid];
        e0[tid] = g_abg0[64 + tid];
    }
    __syncthreads();
    for (int idx = tid; idx < 4096; idx += 128) {
        int k = idx >> 6, c = idx & 63;
        int n = g_gi[cidx*64 + k];
        float z = g_A[(b*NPTS + n)*64 + c] - dsh[c];
        hsh[c*68 + k] = fmaxf(0.f, a0[c]*z + e0[c]);
    }
    __syncthreads();

    int rg = tid & 7;      // rows k = rg*8 + i
    int cg = tid >> 3;     // ch   c = cg*8 + p*2 + {0,1}
    u64 acc[8][4];
#pragma unroll
    for (int i = 0; i < 8; i++)
#pragma unroll
        for (int p = 0; p < 4; p++) acc[i][p] = 0ull;
    const u64* w64 = (const u64*)wsh;
#pragma unroll 2
    for (int cc = 0; cc < 64; cc++) {
        ulonglong2 wa = *(const ulonglong2*)&w64[cc*64 + cg*4];
        ulonglong2 wb = *(const ulonglong2*)&w64[cc*64 + cg*4 + 2];
        float4 ha = *(float4*)&hsh[cc*68 + rg*8];
        float4 hb = *(float4*)&hsh[cc*68 + rg*8 + 4];
        float hv[8] = {ha.x, ha.y, ha.z, ha.w, hb.x, hb.y, hb.z, hb.w};
#pragma unroll
        for (int i = 0; i < 8; i++) {
            u64 h2 = pk2(hv[i]);
            fma2(acc[i][0], h2, wa.x);
            fma2(acc[i][1], h2, wa.y);
            fma2(acc[i][2], h2, wb.x);
            fma2(acc[i][3], h2, wb.y);
        }
    }

    // epilogue, streamed per accumulator column p (two channels at a time)
#pragma unroll
    for (int p = 0; p < 4; p++) {
        float lo[8], hi[8];
#pragma unroll
        for (int i = 0; i < 8; i++) upk(lo[i], hi[i], acc[i][p]);
#pragma unroll
        for (int jj = 0; jj < 2; jj++) {
            int c = cg*8 + p*2 + jj;
            float bb = bg1[c];
            float mx = -FBIG, mn = FBIG, s1 = 0.f, s2 = 0.f;
#pragma unroll
            for (int i = 0; i < 8; i++) {
                float z = (jj ? hi[i] : lo[i]) + bb;
                mx = fmaxf(mx, z); mn = fminf(mn, z);
                s1 += z; s2 += z*z;
            }
#pragma unroll
            for (int o = 1; o < 8; o <<= 1) {
                mx = fmaxf(mx, __shfl_xor_sync(0xffffffffu, mx, o));
                mn = fminf(mn, __shfl_xor_sync(0xffffffffu, mn, o));
                s1 += __shfl_xor_sync(0xffffffffu, s1, o);
                s2 += __shfl_xor_sync(0xffffffffu, s2, o);
            }
            if (rg == 0) {
                g_zmx[cidx*128 + c] = mx;
                g_zmn[cidx*128 + c] = mn;
                g_pg1[cidx*256 + c] = s1;
                g_pg1[cidx*256 + 128 + c] = s2;
            }
        }
    }
}

// ---------------- 7a) semantic output: gather-max of pre-BN z1, monotone BN+relu ----
__global__ __launch_bounds__(128) void k_outsem(float* __restrict__ out) {
    int c = threadIdx.x;
    int cidx = blockIdx.x;
    int b = cidx >> 10;
    float a = g_ab1[c], e = g_ab1[128 + c];
    const int* g = g_gi + cidx*64;
    bool posa = (a >= 0.f);
    float m = posa ? -FBIG : FBIG;
#pragma unroll 4
    for (int k = 0; k < 64; k++) {
        int n = g[k];
        float z = g_z1[(b*NPTS + n)*128 + c];
        m = posa ? fmaxf(m, z) : fminf(m, z);
    }
    out[cidx*128 + c] = fmaxf(0.f, a*m + e);
}

// ---------------- 7b) geo output from zmax/zmin ----------------
__global__ __launch_bounds__(128) void k_outgeo(float* __restrict__ out) {
    int c = threadIdx.x;
    int cidx = blockIdx.x;
    float a = g_abg1[c], e = g_abg1[128 + c];
    float m = (a >= 0.f) ? g_zmx[cidx*128 + c] : g_zmn[cidx*128 + c];
    out[(BSC + cidx)*128 + c] = fmaxf(0.f, a*m + e);
}

// =============================== host ===============================
extern "C" void kernel_launch(void* const* d_in, const int* in_sizes, int n_in,
                              void* d_out, int out_size) {
    const float* pos  = (const float*)d_in[0];
    const float* feat = (const float*)d_in[1];
    const float* w0   = (const float*)d_in[2];
    const float* b0   = (const float*)d_in[3];
    const float* gm0  = (const float*)d_in[4];
    const float* bt0  = (const float*)d_in[5];
    const float* w1   = (const float*)d_in[6];
    const float* b1   = (const float*)d_in[7];
    const float* gm1  = (const float*)d_in[8];
    const float* bt1  = (const float*)d_in[9];
    const float* wg0  = (const float*)d_in[10];
    const float* bg0  = (const float*)d_in[11];
    const float* gmg0 = (const float*)d_in[12];
    const float* btg0 = (const float*)d_in[13];
    const float* wg1  = (const float*)d_in[14];
    const float* bg1  = (const float*)d_in[15];
    const float* gmg1 = (const float*)d_in[16];
    const float* btg1 = (const float*)d_in[17];
    float* out = (float*)d_out;

    cudaFuncSetAttribute(k_front, cudaFuncAttributeMaxDynamicSharedMemorySize, 49408);
    cudaFuncSetAttribute(k_group, cudaFuncAttributeMaxDynamicSharedMemorySize, 67840);
    cudaFuncSetAttribute(k_z1,    cudaFuncAttributeMaxDynamicSharedMemorySize, 50176);
    cudaFuncSetAttribute(k_geo,   cudaFuncAttributeMaxDynamicSharedMemorySize, 50176);

    k_zero<<<64, 1024>>>();
    k_front<<<16 + 1024 + 8192, 512, 49408>>>(pos, feat, w0, b0, wg0, bg0);
    k_group<<<dim3(64, NBATCH), 128, 67840>>>(pos);

    // semantic branch
    k_stat0<<<256, 256>>>();
    k_fin<<<1, 64>>>(0, 256, gm0, bt0);
    k_z1<<<BNP/64, 256, 50176>>>(w1, b1);
    k_stat1<<<256, 256>>>();
    k_fin<<<1, 128>>>(1, 256, gm1, bt1);

    // geo branch
    k_D<<<BSC/4, 256>>>(wg0);
    k_g0stats<<<1024, 64>>>();
    k_redg0<<<16, 128>>>();
    k_fin<<<1, 64>>>(2, 16, gmg0, btg0);
    k_geo<<<BSC, 128, 50176>>>(wg1, bg1);
    k_red<<<256, 256>>>();
    k_fin<<<1, 128>>>(3, 256, gmg1, btg1);

    // outputs
    k_outsem<<<BSC, 128>>>(out);
    k_outgeo<<<BSC, 128>>>(out);
    (void)in_sizes; (void)n_in; (void)out_size;
}